// round 4
// baseline (speedup 1.0000x reference)
#include <cuda_runtime.h>
#include <math.h>

#define HD 128
#define NN 256
#define NB 16

// Scratch (allocation-free rule: __device__ globals)
__device__ float g_h[NN][HD];    // layer-2 output (relu)
__device__ float g_P[32][HD];    // per-block partial sums of dinv*h (for scan)
__device__ float g_A0[NN][HD];   // h3 @ W1a + b1   (batch 0)
__device__ float g_B0[NN][HD];   // h3 @ W1b        (batch 0)
__device__ float g_pb[NB];       // constant edge prob per batch (b>=1)

#define PREFETCH(SRC) do { const float4* _s = (SRC); \
    _Pragma("unroll") for (int _i = 0; _i < 8; _i++) q[_i] = _s[_i * 256 + tid]; } while (0)
#define COMMIT() do { float4* _b = (float4*)buf; \
    _Pragma("unroll") for (int _i = 0; _i < 8; _i++) _b[_i * 256 + tid] = q[_i]; } while (0)

// ---------------------------------------------------------------------------
// K1: blocks 0..31  : batch-0 (emb -> u -> closed-form layer-1 + scan ->
//                     layer-2 GEMM), all weights staged through smem with
//                     register prefetch. Emits g_h rows + g_P partials.
//     blocks 32..46 : node-constant chains for b = 1..15 -> g_pb,
//                     11 staged 32KB weight halves.
// grid 47 x 256
// ---------------------------------------------------------------------------
__global__ void k1(const float* __restrict__ z, const float* __restrict__ We,
                   const float* __restrict__ be, const float* __restrict__ Wg,
                   const float* __restrict__ bg, const float* __restrict__ W1a,
                   const float* __restrict__ W1b, const float* __restrict__ b1,
                   const float* __restrict__ W2, const float* __restrict__ b2) {
    __shared__ __align__(16) float buf[8192];   // 32KB staging buffer
    __shared__ __align__(16) float gs[8][HD];
    __shared__ __align__(16) float hs[8][HD];
    __shared__ float zs[64];
    __shared__ float vv[HD];
    __shared__ float ds[272];
    __shared__ float wsum[8];
    int tid = threadIdx.x, bk = blockIdx.x;
    int d = tid & 127;
    float4 q[8];

    if (bk < 32) {
        // ---- batch 0 path ----
        PREFETCH((const float4*)We);                    // We is exactly 64x128 = 32KB
        if (tid < 64) zs[tid] = z[tid];
        ds[tid] = rsqrtf((float)(tid + 1));
        if (tid < 16) ds[256 + tid] = rsqrtf((float)(257 + tid));
        COMMIT();
        __syncthreads();

        PREFETCH((const float4*)Wg);                    // Wg0 half 0
        float emb = 0.f;
        if (tid < 128) {
            float a0 = 0.f, a1 = 0.f;
#pragma unroll 8
            for (int k = 0; k < 64; k += 2) {
                a0 = fmaf(zs[k],     buf[k * HD + d],       a0);
                a1 = fmaf(zs[k + 1], buf[(k + 1) * HD + d], a1);
            }
            emb = a0 + a1 + be[d];
        }
        __syncthreads();
        COMMIT();
        if (tid < 128) vv[d] = emb;
        __syncthreads();

        PREFETCH((const float4*)Wg + 2048);             // Wg0 half 1
        float u = 0.f;
        if (tid < 128) {
            float a0 = 0.f, a1 = 0.f;
#pragma unroll 8
            for (int k = 0; k < 64; k += 2) {
                a0 = fmaf(vv[k],     buf[k * HD + d],       a0);
                a1 = fmaf(vv[k + 1], buf[(k + 1) * HD + d], a1);
            }
            u = a0 + a1;
        }
        __syncthreads();
        COMMIT();
        __syncthreads();

        PREFETCH((const float4*)(Wg + HD * HD));        // layer-2 weight half 0
        if (tid < 128) {
            float a0 = 0.f, a1 = 0.f;
#pragma unroll 8
            for (int k = 0; k < 64; k += 2) {
                a0 = fmaf(vv[64 + k],     buf[k * HD + d],       a0);
                a1 = fmaf(vv[64 + k + 1], buf[(k + 1) * HD + d], a1);
            }
            u += a0 + a1;
        }
        // closed-form layer-1 + exclusive dinv-scan up to this block's rows
        // (hides the layer-2 weight prefetch latency)
        if (tid < 128) {
            float bg0 = bg[d];
            float c = 0.f, Dex = 0.f;
            int base = bk * 8;
            for (int j = 0; j < base + 8; j++) {
                float dv = ds[j];
                float sc = fmaf(dv, Dex, dv * dv);
                float h1 = fmaxf(fmaf(sc, u, bg0), 0.f);
                if (j >= base) gs[j - base][d] = fmaf(dv, c, dv * dv * h1);
                c = fmaf(dv, h1, c);
                Dex += dv;
            }
        }
        __syncthreads();
        COMMIT();
        __syncthreads();

        // layer-2 GEMM: warp-per-row, two 64-k halves
        int warp = tid >> 5, lane = tid & 31;
        float4 acc = ((const float4*)(bg + HD))[lane];
        PREFETCH((const float4*)(Wg + HD * HD) + 2048); // layer-2 weight half 1
        {
            const float4* Ws4 = (const float4*)buf;
#pragma unroll 8
            for (int k = 0; k < 64; k++) {
                float g = gs[warp][k];
                float4 w = Ws4[k * 32 + lane];
                acc.x = fmaf(g, w.x, acc.x); acc.y = fmaf(g, w.y, acc.y);
                acc.z = fmaf(g, w.z, acc.z); acc.w = fmaf(g, w.w, acc.w);
            }
        }
        __syncthreads();
        COMMIT();
        __syncthreads();
        {
            const float4* Ws4 = (const float4*)buf;
#pragma unroll 8
            for (int k = 0; k < 64; k++) {
                float g = gs[warp][64 + k];
                float4 w = Ws4[k * 32 + lane];
                acc.x = fmaf(g, w.x, acc.x); acc.y = fmaf(g, w.y, acc.y);
                acc.z = fmaf(g, w.z, acc.z); acc.w = fmaf(g, w.w, acc.w);
            }
        }
        acc.x = fmaxf(acc.x, 0.f); acc.y = fmaxf(acc.y, 0.f);
        acc.z = fmaxf(acc.z, 0.f); acc.w = fmaxf(acc.w, 0.f);
        int base = bk * 8;
        ((float4*)&g_h[base + warp][0])[lane] = acc;
        float dj = ds[base + warp];
        ((float4*)&hs[warp][0])[lane] = make_float4(acc.x*dj, acc.y*dj, acc.z*dj, acc.w*dj);
        __syncthreads();
        if (tid < HD) {
            float s = 0.f;
#pragma unroll
            for (int w = 0; w < 8; w++) s += hs[w][tid];
            g_P[bk][tid] = s;
        }
    } else {
        // ---- node-constant chain for batch b = bk-31 ----
        int b = bk - 31;
        PREFETCH((const float4*)We);
        if (tid < 64) zs[tid] = z[b * 64 + tid];
        COMMIT();
        __syncthreads();

        PREFETCH((const float4*)Wg);                    // stage 0 source
        float emb = 0.f;
        if (tid < 128) {
            float a0 = 0.f, a1 = 0.f;
#pragma unroll 8
            for (int k = 0; k < 64; k += 2) {
                a0 = fmaf(zs[k],     buf[k * HD + d],       a0);
                a1 = fmaf(zs[k + 1], buf[(k + 1) * HD + d], a1);
            }
            emb = a0 + a1 + be[d];
        }
        __syncthreads();
        COMMIT();
        if (tid < 128) vv[d] = emb;
        __syncthreads();

        // stages 0..9: Wg0h0, Wg0h1, Wg1h0, Wg1h1, Wg2h0, Wg2h1, W1a0, W1a1, W1b0, W1b1
        float accL = 0.f, aA = 0.f, aB = 0.f;
#pragma unroll
        for (int idx = 0; idx < 10; idx++) {
            if (idx < 9) {
                int nx = idx + 1, grp = nx >> 1;
                const float* basep = (grp < 3) ? (Wg + grp * HD * HD)
                                   : (grp == 3 ? W1a : W1b);
                PREFETCH((const float4*)(basep + (nx & 1) * 64 * HD));
            }
            if (tid < 128) {
                int hh = idx & 1;
                float a0 = 0.f, a1 = 0.f;
#pragma unroll 8
                for (int k = 0; k < 64; k += 2) {
                    a0 = fmaf(vv[hh * 64 + k],     buf[k * HD + d],       a0);
                    a1 = fmaf(vv[hh * 64 + k + 1], buf[(k + 1) * HD + d], a1);
                }
                float pt = a0 + a1;
                if (idx < 6)      accL += pt;
                else if (idx < 8) aA += pt;
                else              aB += pt;
            }
            __syncthreads();
            if (idx < 9) COMMIT();
            if ((idx == 1 || idx == 3 || idx == 5) && tid < 128) {
                vv[d] = fmaxf(accL + bg[(idx >> 1) * HD + d], 0.f);
            }
            __syncthreads();
            if (idx == 1 || idx == 3 || idx == 5) accL = 0.f;
        }
        // logit = sum_d relu(aA + b1 + aB) * W2 + b2 -> sigmoid
        float t = 0.f;
        if (tid < 128) t = fmaxf(aA + b1[d] + aB, 0.f) * W2[d];
        for (int off = 16; off > 0; off >>= 1)
            t += __shfl_down_sync(0xffffffffu, t, off);
        if ((tid & 31) == 0) wsum[tid >> 5] = t;
        __syncthreads();
        if (tid == 0) {
            float s = wsum[0] + wsum[1] + wsum[2] + wsum[3]
                    + wsum[4] + wsum[5] + wsum[6] + wsum[7] + b2[0];
            g_pb[b] = 1.f / (1.f + __expf(-s));
        }
    }
}

// ---------------------------------------------------------------------------
// K2: block-prefix scan -> layer-3 GEMM+ReLU -> one of {A0, B0} GEMM.
// grid 64 x 256: blk = bk*2 + sel  (sel 0 -> W1a/g_A0, 1 -> W1b/g_B0)
// ---------------------------------------------------------------------------
__global__ void k2(const float* __restrict__ Wg2, const float* __restrict__ bg2,
                   const float* __restrict__ W1a, const float* __restrict__ W1b,
                   const float* __restrict__ b1) {
    __shared__ __align__(16) float buf[8192];
    __shared__ __align__(16) float gs[8][HD];
    __shared__ __align__(16) float hs[8][HD];
    int tid = threadIdx.x;
    int bk = blockIdx.x >> 1, sel = blockIdx.x & 1;
    int base = bk * 8;
    int warp = tid >> 5, lane = tid & 31;
    const float* WX = sel ? W1b : W1a;
    float4 q[8];

    PREFETCH((const float4*)Wg2);                       // Wg2 half 0
    if (tid < 128) {
        float c = 0.f;
        for (int p = 0; p < bk; p++) c += g_P[p][tid];
#pragma unroll
        for (int j = 0; j < 8; j++) {
            int n = base + j;
            float dv = rsqrtf((float)(n + 1));
            float h = g_h[n][tid];
            gs[j][tid] = fmaf(dv, c, dv * dv * h);
            c = fmaf(dv, h, c);
        }
    }
    COMMIT();
    __syncthreads();

    PREFETCH((const float4*)Wg2 + 2048);                // Wg2 half 1
    float4 acc = ((const float4*)bg2)[lane];
    {
        const float4* Ws4 = (const float4*)buf;
#pragma unroll 8
        for (int k = 0; k < 64; k++) {
            float g = gs[warp][k];
            float4 w = Ws4[k * 32 + lane];
            acc.x = fmaf(g, w.x, acc.x); acc.y = fmaf(g, w.y, acc.y);
            acc.z = fmaf(g, w.z, acc.z); acc.w = fmaf(g, w.w, acc.w);
        }
    }
    __syncthreads();
    COMMIT();
    __syncthreads();

    PREFETCH((const float4*)WX);                        // W1x half 0
    {
        const float4* Ws4 = (const float4*)buf;
#pragma unroll 8
        for (int k = 0; k < 64; k++) {
            float g = gs[warp][64 + k];
            float4 w = Ws4[k * 32 + lane];
            acc.x = fmaf(g, w.x, acc.x); acc.y = fmaf(g, w.y, acc.y);
            acc.z = fmaf(g, w.z, acc.z); acc.w = fmaf(g, w.w, acc.w);
        }
    }
    acc.x = fmaxf(acc.x, 0.f); acc.y = fmaxf(acc.y, 0.f);
    acc.z = fmaxf(acc.z, 0.f); acc.w = fmaxf(acc.w, 0.f);
    ((float4*)&hs[warp][0])[lane] = acc;                // h3 rows
    __syncthreads();
    COMMIT();
    __syncthreads();

    PREFETCH((const float4*)WX + 2048);                 // W1x half 1
    float4 aX = sel ? make_float4(0.f, 0.f, 0.f, 0.f)
                    : ((const float4*)b1)[lane];
    {
        const float4* Ws4 = (const float4*)buf;
#pragma unroll 8
        for (int k = 0; k < 64; k++) {
            float h = hs[warp][k];
            float4 w = Ws4[k * 32 + lane];
            aX.x = fmaf(h, w.x, aX.x); aX.y = fmaf(h, w.y, aX.y);
            aX.z = fmaf(h, w.z, aX.z); aX.w = fmaf(h, w.w, aX.w);
        }
    }
    __syncthreads();
    COMMIT();
    __syncthreads();
    {
        const float4* Ws4 = (const float4*)buf;
#pragma unroll 8
        for (int k = 0; k < 64; k++) {
            float h = hs[warp][64 + k];
            float4 w = Ws4[k * 32 + lane];
            aX.x = fmaf(h, w.x, aX.x); aX.y = fmaf(h, w.y, aX.y);
            aX.z = fmaf(h, w.z, aX.z); aX.w = fmaf(h, w.w, aX.w);
        }
    }
    if (sel) ((float4*)&g_B0[base + warp][0])[lane] = aX;
    else     ((float4*)&g_A0[base + warp][0])[lane] = aX;
}

// ---------------------------------------------------------------------------
// K3: blocks 0..135 : batch-0 pairwise tiles (16x16, upper triangle, mirrored)
//     blocks 136..147: constant fill for b>=1 (320 rows each, diag 0)
// grid 148 x 256
// ---------------------------------------------------------------------------
__global__ void k3(const float* __restrict__ W2, const float* __restrict__ b2,
                   float* __restrict__ out) {
    int tid = threadIdx.x;
    int blk = blockIdx.x;
    if (blk < 136) {
        int ti = 0, rem = blk;
        while (rem >= 16 - ti) { rem -= 16 - ti; ti++; }
        int tj = ti + rem;

        __shared__ __align__(16) float a_sh[16][132];
        __shared__ __align__(16) float b_sh[16][132];
        __shared__ __align__(16) float w2s[HD];
        __shared__ float b2s;
        __shared__ float tile[16][17];
        for (int i = tid; i < 512; i += 256) {
            int r = i >> 5, d4 = i & 31;
            ((float4*)&a_sh[r][0])[d4] = ((const float4*)&g_A0[ti * 16 + r][0])[d4];
            ((float4*)&b_sh[r][0])[d4] = ((const float4*)&g_B0[tj * 16 + r][0])[d4];
        }
        if (tid < HD) w2s[tid] = W2[tid];
        if (tid == 0) b2s = b2[0];
        __syncthreads();

        int il = tid >> 4, jl = tid & 15;
        const float4* a4 = (const float4*)&a_sh[il][0];
        const float4* b4 = (const float4*)&b_sh[jl][0];
        const float4* w4 = (const float4*)w2s;
        float ac0 = 0.f, ac1 = 0.f, ac2 = 0.f, ac3 = 0.f;
#pragma unroll
        for (int qd = 0; qd < 8; qd++) {
            { float4 a=a4[qd],    b=b4[qd],    w=w4[qd];
              ac0 = fmaf(fmaxf(a.x+b.x,0.f),w.x,ac0); ac0 = fmaf(fmaxf(a.y+b.y,0.f),w.y,ac0);
              ac0 = fmaf(fmaxf(a.z+b.z,0.f),w.z,ac0); ac0 = fmaf(fmaxf(a.w+b.w,0.f),w.w,ac0); }
            { float4 a=a4[qd+8],  b=b4[qd+8],  w=w4[qd+8];
              ac1 = fmaf(fmaxf(a.x+b.x,0.f),w.x,ac1); ac1 = fmaf(fmaxf(a.y+b.y,0.f),w.y,ac1);
              ac1 = fmaf(fmaxf(a.z+b.z,0.f),w.z,ac1); ac1 = fmaf(fmaxf(a.w+b.w,0.f),w.w,ac1); }
            { float4 a=a4[qd+16], b=b4[qd+16], w=w4[qd+16];
              ac2 = fmaf(fmaxf(a.x+b.x,0.f),w.x,ac2); ac2 = fmaf(fmaxf(a.y+b.y,0.f),w.y,ac2);
              ac2 = fmaf(fmaxf(a.z+b.z,0.f),w.z,ac2); ac2 = fmaf(fmaxf(a.w+b.w,0.f),w.w,ac2); }
            { float4 a=a4[qd+24], b=b4[qd+24], w=w4[qd+24];
              ac3 = fmaf(fmaxf(a.x+b.x,0.f),w.x,ac3); ac3 = fmaf(fmaxf(a.y+b.y,0.f),w.y,ac3);
              ac3 = fmaf(fmaxf(a.z+b.z,0.f),w.z,ac3); ac3 = fmaf(fmaxf(a.w+b.w,0.f),w.w,ac3); }
        }
        float accv = (ac0 + ac1) + (ac2 + ac3);
        tile[il][jl] = 1.f / (1.f + __expf(-(accv + b2s)));
        __syncthreads();

        int r = tid >> 4, c = tid & 15;
        if (ti == tj) {
            float vo = (r < c) ? tile[r][c] : ((r > c) ? tile[c][r] : 0.f);
            out[((size_t)(ti * 16 + r)) * NN + ti * 16 + c] = vo;
        } else {
            out[((size_t)(ti * 16 + r)) * NN + tj * 16 + c] = tile[r][c];
            out[((size_t)(tj * 16 + r)) * NN + ti * 16 + c] = tile[c][r];
        }
    } else {
        // fill: 12 blocks x 320 rows; global fill-row gr in [0, 3840)
        __shared__ float pbs[NB];
        if (tid < NB) pbs[tid] = g_pb[tid];
        __syncthreads();
        int fid = blk - 136;
        int f4base = fid * 20480;          // block's first float4 (320 rows * 64)
#pragma unroll 4
        for (int t = 0; t < 80; t++) {
            int idx = f4base + t * 256 + tid;
            int gr = idx >> 6;             // fill row 0..3839
            int c4 = idx & 63;
            int b = (gr >> 8) + 1;
            int i = gr & 255;
            float p = pbs[b];
            int j0 = c4 * 4;
            float4 vo;
            vo.x = (i == j0 + 0) ? 0.f : p;
            vo.y = (i == j0 + 1) ? 0.f : p;
            vo.z = (i == j0 + 2) ? 0.f : p;
            vo.w = (i == j0 + 3) ? 0.f : p;
            ((float4*)out)[((size_t)b * NN * NN + (size_t)i * NN) / 4 + c4] = vo;
        }
    }
}

// ---------------------------------------------------------------------------
extern "C" void kernel_launch(void* const* d_in, const int* in_sizes, int n_in,
                              void* d_out, int out_size) {
    const float* z   = (const float*)d_in[0];
    const float* We  = (const float*)d_in[1];
    const float* be  = (const float*)d_in[2];
    const float* Wg  = (const float*)d_in[3];
    const float* bg  = (const float*)d_in[4];
    const float* W1a = (const float*)d_in[5];
    const float* W1b = (const float*)d_in[6];
    const float* b1  = (const float*)d_in[7];
    const float* W2  = (const float*)d_in[8];
    const float* b2  = (const float*)d_in[9];
    float* out = (float*)d_out;

    k1<<<47, 256>>>(z, We, be, Wg, bg, W1a, W1b, b1, W2, b2);
    k2<<<64, 256>>>(Wg + 2 * HD * HD, bg + 2 * HD, W1a, W1b, b1);
    k3<<<148, 256>>>(W2, b2, out);
}